// round 16
// baseline (speedup 1.0000x reference)
#include <cuda_runtime.h>

// BatchDelayProcessor: lag-D feedback delay line.
//   c_k = x_k + FB * c_{k-1}         (carry per chain, c_{-1} = 0)
//   out_k = (1-MIX) * x_k + MIX * c_{k-1}
// Each (b, j) with j in [0, D) is an independent length-NBLK chain:
// one thread owns one float2 chain, fully unrolled over the 20 k-blocks.
//
// TERMINAL KERNEL (ties session best, 39.36us e2e).
// Exact-fit launch: 705600 chains = 2450 CTAs x 288 threads (9 warps) —
// no tail, no bounds check.
//
// Roofline, validated over 15 rounds: steady-state graph-replay traffic is
// compulsory 226 MB/launch (113 MB input re-read — the output's dirty fill
// evicts x from the 126 MB L2; every replacement-policy control
// (evict_last/evict_first createpolicy, .cs, .wt) is inert at the default
// carveout — plus 113 MB writeback), at the ~5.5-5.7 TB/s device ceiling
// for an interleaved 50/50 R/W stream. The ceiling is occupancy- and
// MLP-invariant (41% occ @ MLP=10 == 82% occ @ MLP=2), width-optimal at
// coalesced 64-bit (smem-staged 128-bit: -47%), and wave-shape-optimal with
// a free scheduler (persistent single-wave: -9%). 226 MB / 5.7 TB/s ~= 39.4us.

#define D_SAMP   22050
#define T_LEN    441000
#define B_SZ     64
#define NBLK     20          // T_LEN / D_SAMP
#define FB       0.3f
#define MIXC     0.5f

// float2 vectorization: D_SAMP % 2 == 0
#define HD       (D_SAMP / 2)            // 11025 float2 chains per batch row
#define NCHAINS  (B_SZ * HD)             // 705600 = 2450 * 288 exactly

#define CTA_THREADS 288                  // 9 warps; exact-fit grid
#define GRID_CTAS   (NCHAINS / CTA_THREADS)   // 2450

__global__ __launch_bounds__(CTA_THREADS) void delay_kernel(const float* __restrict__ x,
                                                            float* __restrict__ out) {
    int idx = blockIdx.x * CTA_THREADS + threadIdx.x;   // always < NCHAINS

    int b = idx / HD;
    int j = (idx - b * HD) * 2;

    const char* xbase = (const char*)(x + (size_t)b * T_LEN + j);
    char*       obase = (char*)(out + (size_t)b * T_LEN + j);

    float2 c;
    c.x = 0.0f;
    c.y = 0.0f;

    const size_t blk_stride = (size_t)D_SAMP * sizeof(float);  // 88200 B

#pragma unroll
    for (int k = 0; k < NBLK; k++) {
        float2 xv = *reinterpret_cast<const float2*>(xbase + (size_t)k * blk_stride);
        float2 o;
        // out = x*(1-MIX) + c*MIX
        o.x = fmaf(c.x, MIXC, xv.x * (1.0f - MIXC));
        o.y = fmaf(c.y, MIXC, xv.y * (1.0f - MIXC));
        *reinterpret_cast<float2*>(obase + (size_t)k * blk_stride) = o;
        // c = x + FB*c
        c.x = fmaf(c.x, FB, xv.x);
        c.y = fmaf(c.y, FB, xv.y);
    }
}

extern "C" void kernel_launch(void* const* d_in, const int* in_sizes, int n_in,
                              void* d_out, int out_size) {
    const float* x = (const float*)d_in[0];
    float* out = (float*)d_out;
    delay_kernel<<<GRID_CTAS, CTA_THREADS>>>(x, out);
}

// round 17
// speedup vs baseline: 1.0584x; 1.0584x over previous
#include <cuda_runtime.h>

// BatchDelayProcessor: lag-D feedback delay line.
//   c_k = x_k + FB * c_{k-1}         (carry per chain, c_{-1} = 0)
//   out_k = (1-MIX) * x_k + MIX * c_{k-1}
// Each (b, j) with j in [0, D) is an independent length-NBLK chain:
// one thread owns one float2 chain, fully unrolled over the 20 k-blocks.
//
// TERMINAL KERNEL (session best 39.36us e2e, measured twice).
// Exact-fit launch: 705600 chains = 2450 CTAs x 288 threads (9 warps) —
// no tail, no bounds check.
//
// Roofline, validated over 16 rounds: steady-state graph-replay traffic is
// compulsory 226 MB/launch (113 MB input re-read — the output's dirty fill
// evicts x from the 126 MB L2; every replacement-policy control
// (evict_last/evict_first createpolicy, .cs, .wt) is inert at the default
// carveout — plus 113 MB writeback), at the ~5.5-5.7 TB/s device ceiling
// for an interleaved 50/50 R/W stream. Ceiling is occupancy- and
// MLP-invariant (41% occ @ MLP=10 == 82% occ @ MLP=2), width-optimal at
// coalesced 64-bit (smem-staged 128-bit: -47%), wave-shape-optimal with a
// free scheduler (persistent single-wave: -9%). R16 note: identical binary
// measured 39.36 and 41.73 on different holds -> cross-hold DVFS/chip
// variance ~+/-2us; do not fit code changes to it.

#define D_SAMP   22050
#define T_LEN    441000
#define B_SZ     64
#define NBLK     20          // T_LEN / D_SAMP
#define FB       0.3f
#define MIXC     0.5f

// float2 vectorization: D_SAMP % 2 == 0
#define HD       (D_SAMP / 2)            // 11025 float2 chains per batch row
#define NCHAINS  (B_SZ * HD)             // 705600 = 2450 * 288 exactly

#define CTA_THREADS 288                  // 9 warps; exact-fit grid
#define GRID_CTAS   (NCHAINS / CTA_THREADS)   // 2450

__global__ __launch_bounds__(CTA_THREADS) void delay_kernel(const float* __restrict__ x,
                                                            float* __restrict__ out) {
    int idx = blockIdx.x * CTA_THREADS + threadIdx.x;   // always < NCHAINS

    int b = idx / HD;
    int j = (idx - b * HD) * 2;

    const char* xbase = (const char*)(x + (size_t)b * T_LEN + j);
    char*       obase = (char*)(out + (size_t)b * T_LEN + j);

    float2 c;
    c.x = 0.0f;
    c.y = 0.0f;

    const size_t blk_stride = (size_t)D_SAMP * sizeof(float);  // 88200 B

#pragma unroll
    for (int k = 0; k < NBLK; k++) {
        float2 xv = *reinterpret_cast<const float2*>(xbase + (size_t)k * blk_stride);
        float2 o;
        // out = x*(1-MIX) + c*MIX
        o.x = fmaf(c.x, MIXC, xv.x * (1.0f - MIXC));
        o.y = fmaf(c.y, MIXC, xv.y * (1.0f - MIXC));
        *reinterpret_cast<float2*>(obase + (size_t)k * blk_stride) = o;
        // c = x + FB*c
        c.x = fmaf(c.x, FB, xv.x);
        c.y = fmaf(c.y, FB, xv.y);
    }
}

extern "C" void kernel_launch(void* const* d_in, const int* in_sizes, int n_in,
                              void* d_out, int out_size) {
    const float* x = (const float*)d_in[0];
    float* out = (float*)d_out;
    delay_kernel<<<GRID_CTAS, CTA_THREADS>>>(x, out);
}